// round 16
// baseline (speedup 1.0000x reference)
#include <cuda_runtime.h>
#include <cuda_fp16.h>

// Fixed problem shape (SimpleGNN): N=100000 nodes, E=1600000 edges, dims 64->64->64
#define MAXN 100000
#define MAXE 1600000
#define SEG  64   // padded CSR segment per node (max degree ~45 << 64)

// Scratch (device globals -- no runtime allocation allowed)
__device__ __half g_hbuf[MAXN * 64];     // fp16 pre-scaled message table
__device__ __half g_hact[MAXN * 64];     // fp16 hidden activations (layer-1 output)
__device__ int    g_indeg[MAXN];         // zeroed by agg2 after last use (replay invariant)
__device__ unsigned short g_rank[MAXE];  // within-node rank of each edge (from hist)
__device__ int    g_csr[MAXN * SEG];     // padded CSR: node v owns [v*SEG, v*SEG+indeg[v])
// (zero-initialized globals cover call 1; agg2 re-zeroes indeg every call)

// ---------------------------------------------------------------------------
// f32x2 packed-FMA helpers (sm_10x FFMA2 -- only reachable via PTX)
// ---------------------------------------------------------------------------
__device__ __forceinline__ void ffma2(unsigned long long& acc,
                                      unsigned long long a, unsigned long long b) {
    asm("fma.rn.f32x2 %0, %1, %2, %0;" : "+l"(acc) : "l"(a), "l"(b));
}
__device__ __forceinline__ unsigned long long pack2(float v) {
    unsigned long long r;
    asm("mov.b64 %0, {%1, %1};" : "=l"(r) : "f"(v));
    return r;
}
__device__ __forceinline__ float2 unpack2(unsigned long long v) {
    float2 r;
    asm("mov.b64 {%0, %1}, %2;" : "=f"(r.x), "=f"(r.y) : "l"(v));
    return r;
}
__device__ __forceinline__ unsigned h2_bits(__half2 h) {
    return *reinterpret_cast<unsigned*>(&h);
}
__device__ __forceinline__ float2 h2f2(unsigned bits) {
    return __half22float2(*reinterpret_cast<__half2*>(&bits));
}

// ---------------------------------------------------------------------------
// Histogram of in-degrees + per-edge rank (ushort: max degree << 65536)
// ---------------------------------------------------------------------------
__global__ void k_hist(const int* __restrict__ dst, int E) {
    int i = (blockIdx.x * blockDim.x + threadIdx.x) * 4;
    if (i + 4 <= E) {
        int4 d = __ldg((const int4*)(dst + i));
        ushort4 r;
        r.x = (unsigned short)atomicAdd(&g_indeg[d.x], 1);
        r.y = (unsigned short)atomicAdd(&g_indeg[d.y], 1);
        r.z = (unsigned short)atomicAdd(&g_indeg[d.z], 1);
        r.w = (unsigned short)atomicAdd(&g_indeg[d.w], 1);
        *(ushort4*)(g_rank + i) = r;
    } else {
        for (; i < E; i++)
            g_rank[i] = (unsigned short)atomicAdd(&g_indeg[dst[i]], 1);
    }
}

// Atomic-free scatter into padded CSR: pos = dst*SEG + rank. No scan needed.
__global__ void k_fill(const int* __restrict__ src, const int* __restrict__ dst, int E) {
    int i = (blockIdx.x * blockDim.x + threadIdx.x) * 4;
    if (i + 4 <= E) {
        int4 s = __ldg((const int4*)(src + i));
        int4 d = __ldg((const int4*)(dst + i));
        ushort4 r = *(const ushort4*)(g_rank + i);
        g_csr[d.x * SEG + r.x] = s.x;
        g_csr[d.y * SEG + r.y] = s.y;
        g_csr[d.z * SEG + r.z] = s.z;
        g_csr[d.w * SEG + r.w] = s.w;
    } else {
        for (; i < E; i++) {
            g_csr[dst[i] * SEG + g_rank[i]] = src[i];
        }
    }
}

// ---------------------------------------------------------------------------
// GEMM + fused dinv-scale + fp16 store: m[r] = fp16(dinv[r] * (X@W)[r]),
// dinv computed inline from indeg. T = float (layer 1) or __half (layer 2).
// 128 threads/block, 128 rows/block; 8x8 tile/thread via packed f32x2 FMA.
// ---------------------------------------------------------------------------
template <typename T>
__global__ __launch_bounds__(128) void k_gemm64h(const T* __restrict__ X,
                                                 const float* __restrict__ W,
                                                 __half* __restrict__ Yh, int n) {
    __shared__ float Ws[64 * 64];
    __shared__ float Xs[128 * 65];  // pad to 65 to avoid bank conflicts

    int t = threadIdx.x;
    #pragma unroll
    for (int i = t; i < 4096; i += 128) Ws[i] = W[i];

    int row0 = blockIdx.x * 128;
    for (int i = t; i < 8192; i += 128) {
        int r = i >> 6, c = i & 63;
        int gr = row0 + r;
        Xs[r * 65 + c] = (gr < n) ? (float)X[gr * 64 + c] : 0.f;
    }
    __syncthreads();

    int cg = t & 7;       // column group: cols [cg*8, cg*8+8)
    int rg = t >> 3;      // row group:    rows [rg*8, rg*8+8)

    unsigned long long acc[8][4];
    #pragma unroll
    for (int i = 0; i < 8; i++)
        #pragma unroll
        for (int j = 0; j < 4; j++) acc[i][j] = 0ull;

    #pragma unroll 4
    for (int k = 0; k < 64; k++) {
        ulonglong2 wA = *(const ulonglong2*)&Ws[k * 64 + cg * 8];
        ulonglong2 wB = *(const ulonglong2*)&Ws[k * 64 + cg * 8 + 4];
        #pragma unroll
        for (int i = 0; i < 8; i++) {
            unsigned long long xp = pack2(Xs[(rg * 8 + i) * 65 + k]);
            ffma2(acc[i][0], xp, wA.x);
            ffma2(acc[i][1], xp, wA.y);
            ffma2(acc[i][2], xp, wB.x);
            ffma2(acc[i][3], xp, wB.y);
        }
    }

    #pragma unroll
    for (int i = 0; i < 8; i++) {
        int gr = row0 + rg * 8 + i;
        if (gr < n) {
            float dv = rsqrtf((float)(__ldg(&g_indeg[gr]) + 1));
            float2 p0 = unpack2(acc[i][0]), p1 = unpack2(acc[i][1]);
            float2 p2 = unpack2(acc[i][2]), p3 = unpack2(acc[i][3]);
            uint4 pk;
            pk.x = h2_bits(__floats2half2_rn(p0.x * dv, p0.y * dv));
            pk.y = h2_bits(__floats2half2_rn(p1.x * dv, p1.y * dv));
            pk.z = h2_bits(__floats2half2_rn(p2.x * dv, p2.y * dv));
            pk.w = h2_bits(__floats2half2_rn(p3.x * dv, p3.y * dv));
            *(uint4*)&Yh[gr * 64 + cg * 8] = pk;
        }
    }
}

// ---------------------------------------------------------------------------
// Pull aggregation with paired-edge gathers (R9 champion configuration),
// padded-CSR edition: edges live in [v*SEG, v*SEG+indeg[v]); dv inline.
// Warp = 1 node; 2 groups of 16 lanes; group g handles edges (e+2j+g);
// each lane gathers 8B of the 128B row -> one LDG.64 covers TWO edges per j.
// ZERO (agg2 only): lane 31 re-zeroes indeg[v] after use (replay invariant).
// ---------------------------------------------------------------------------
template <bool HOUT, bool ZERO>
__global__ __launch_bounds__(256) void k_agg(const uint2* __restrict__ xw,  // row = 16 uint2
                                             const float* __restrict__ bias,
                                             void* __restrict__ out, int n) {
    int v = (blockIdx.x * 256 + threadIdx.x) >> 5;
    int lane = threadIdx.x & 31;
    if (v >= n) return;
    int g = lane >> 4;       // edge-parity group (0: even edges, 1: odd edges)
    int c = lane & 15;       // 8-byte column slot within the 128B row

    int ind = __ldg(&g_indeg[v]);
    if (ZERO && lane == 31) g_indeg[v] = 0;   // last consumer resets for replay
    float dv = rsqrtf((float)(ind + 1));

    float ax0 = 0.f, ay0 = 0.f, ax1 = 0.f, ay1 = 0.f;

    // self-loop message: group 0 only
    if (g == 0) {
        uint2 m = __ldg(&xw[v * 16 + c]);
        float2 a = h2f2(m.x), b = h2f2(m.y);
        ax0 = a.x; ay0 = a.y; ax1 = b.x; ay1 = b.y;
    }

    int e = v * SEG;
    int end = e + ind;

    // full batches: 16 edges (8 pairs) per iteration, 8 independent LDG.64
    for (; e + 16 <= end; e += 16) {
        #pragma unroll
        for (int j = 0; j < 8; j++) {
            int idx = __ldg(&g_csr[e + 2 * j + g]);
            uint2 m = __ldg(&xw[idx * 16 + c]);
            float2 a = h2f2(m.x), b = h2f2(m.y);
            ax0 += a.x; ay0 += a.y; ax1 += b.x; ay1 += b.y;
        }
    }
    // predicated tail: remaining <16 edges, still 8-deep in flight
    #pragma unroll
    for (int j = 0; j < 8; j++) {
        int ej = e + 2 * j + g;
        if (ej < end) {
            int idx = __ldg(&g_csr[ej]);
            uint2 m = __ldg(&xw[idx * 16 + c]);
            float2 a = h2f2(m.x), b = h2f2(m.y);
            ax0 += a.x; ay0 += a.y; ax1 += b.x; ay1 += b.y;
        }
    }

    // combine the two edge groups
    ax0 += __shfl_down_sync(0xffffffffu, ax0, 16);
    ay0 += __shfl_down_sync(0xffffffffu, ay0, 16);
    ax1 += __shfl_down_sync(0xffffffffu, ax1, 16);
    ay1 += __shfl_down_sync(0xffffffffu, ay1, 16);

    if (g == 0) {
        float4 bv = __ldg((const float4*)(bias + c * 4));
        float r0 = fmaxf(fmaf(ax0, dv, bv.x), 0.f);
        float r1 = fmaxf(fmaf(ay0, dv, bv.y), 0.f);
        float r2 = fmaxf(fmaf(ax1, dv, bv.z), 0.f);
        float r3 = fmaxf(fmaf(ay1, dv, bv.w), 0.f);
        if (HOUT) {
            uint2 o;
            o.x = h2_bits(__floats2half2_rn(r0, r1));
            o.y = h2_bits(__floats2half2_rn(r2, r3));
            ((uint2*)out)[v * 16 + c] = o;
        } else {
            ((float4*)out)[v * 16 + c] = make_float4(r0, r1, r2, r3);
        }
    }
}

// ---------------------------------------------------------------------------
extern "C" void kernel_launch(void* const* d_in, const int* in_sizes, int n_in,
                              void* d_out, int out_size) {
    const float* x  = (const float*)d_in[0];
    const int*   ei = (const int*)d_in[1];
    const float* W1 = (const float*)d_in[2];
    const float* b1 = (const float*)d_in[3];
    const float* W2 = (const float*)d_in[4];
    const float* b2 = (const float*)d_in[5];
    float* out = (float*)d_out;

    int N = in_sizes[0] / 64;
    int E = in_sizes[1] / 2;
    const int* src = ei;
    const int* dst = ei + E;
    int E4 = E / 4;

    int nbE4 = (E4 + 255) / 256;
    int nbAgg = (N + 7) / 8;       // 8 warps per 256-thread block
    int nbGemm = (N + 127) / 128;

    __half* hbuf;  cudaGetSymbolAddress((void**)&hbuf, g_hbuf);
    __half* hact;  cudaGetSymbolAddress((void**)&hact, g_hact);

    // One-time side stream + events (created on the pre-capture correctness
    // call; reused by every call -> identical, deterministic launch pattern).
    static cudaStream_t s1 = nullptr;
    static cudaEvent_t evFork = nullptr, evJoin = nullptr;
    static bool streamsOk = false;
    static bool tried = false;
    if (!tried) {
        tried = true;
        streamsOk = (cudaStreamCreateWithFlags(&s1, cudaStreamNonBlocking) == cudaSuccess) &&
                    (cudaEventCreateWithFlags(&evFork, cudaEventDisableTiming) == cudaSuccess) &&
                    (cudaEventCreateWithFlags(&evJoin, cudaEventDisableTiming) == cudaSuccess);
    }

    // Build: hist (indeg+rank). indeg starts zero (globals on call 1,
    // re-zeroed by agg2 on every call).
    k_hist<<<nbE4, 256>>>(dst, E);

    if (streamsOk) {
        // Fork: GEMM1 (needs indeg only) overlaps fill on the main stream.
        cudaEventRecord(evFork, 0);
        cudaStreamWaitEvent(s1, evFork, 0);
        k_gemm64h<float><<<nbGemm, 128, 0, s1>>>(x, W1, hbuf, N);
        cudaEventRecord(evJoin, s1);

        k_fill<<<nbE4, 256>>>(src, dst, E);

        cudaStreamWaitEvent(0, evJoin, 0);
    } else {
        k_gemm64h<float><<<nbGemm, 128>>>(x, W1, hbuf, N);
        k_fill<<<nbE4, 256>>>(src, dst, E);
    }

    // Layer 1 aggregate (fp16 h), then layer 2 (hbuf reused for m2 -- strictly
    // sequential on the main stream, so no overlap with agg1's reads)
    k_agg<true, false><<<nbAgg, 256>>>((const uint2*)hbuf, b1, hact, N);
    k_gemm64h<__half><<<nbGemm, 128>>>(hact, W2, hbuf, N);
    k_agg<false, true><<<nbAgg, 256>>>((const uint2*)hbuf, b2, out, N);
}

// round 17
// speedup vs baseline: 1.4131x; 1.4131x over previous
#include <cuda_runtime.h>
#include <cuda_fp16.h>

// Fixed problem shape (SimpleGNN): N=100000 nodes, E=1600000 edges, dims 64->64->64
#define MAXN 100000
#define MAXE 1600000

// Scratch (device globals -- no runtime allocation allowed)
__device__ __half g_hbuf[MAXN * 64];   // fp16 pre-scaled message table
__device__ __half g_hact[MAXN * 64];   // fp16 hidden activations (layer-1 output)
__device__ int    g_indeg[MAXN];       // re-zeroed in k_scan3 (replay invariant)
__device__ int    g_incl[MAXN];
__device__ int    g_offs[MAXN + 1];    // exclusive offsets (immutable after scan3)
__device__ unsigned short g_rank[MAXE];// within-node rank of each edge (from hist)
__device__ int    g_csr[MAXE];         // src index only (weight folded into message)
__device__ float  g_dinv[MAXN];
__device__ int    g_bsums[128];        // per-1024-block totals from scan1

// ---------------------------------------------------------------------------
// f32x2 packed-FMA helpers (sm_10x FFMA2 -- only reachable via PTX)
// ---------------------------------------------------------------------------
__device__ __forceinline__ void ffma2(unsigned long long& acc,
                                      unsigned long long a, unsigned long long b) {
    asm("fma.rn.f32x2 %0, %1, %2, %0;" : "+l"(acc) : "l"(a), "l"(b));
}
__device__ __forceinline__ unsigned long long pack2(float v) {
    unsigned long long r;
    asm("mov.b64 %0, {%1, %1};" : "=l"(r) : "f"(v));
    return r;
}
__device__ __forceinline__ float2 unpack2(unsigned long long v) {
    float2 r;
    asm("mov.b64 {%0, %1}, %2;" : "=f"(r.x), "=f"(r.y) : "l"(v));
    return r;
}
__device__ __forceinline__ unsigned h2_bits(__half2 h) {
    return *reinterpret_cast<unsigned*>(&h);
}
__device__ __forceinline__ float2 h2f2(unsigned bits) {
    return __half22float2(*reinterpret_cast<__half2*>(&bits));
}
__device__ __forceinline__ __half2 bits_h2(unsigned bits) {
    return *reinterpret_cast<__half2*>(&bits);
}

// ---------------------------------------------------------------------------
// Histogram of in-degrees + per-edge rank (ushort: max degree << 65536)
// ---------------------------------------------------------------------------
__global__ void k_hist(const int* __restrict__ dst, int E) {
    int i = (blockIdx.x * blockDim.x + threadIdx.x) * 4;
    if (i + 4 <= E) {
        int4 d = __ldg((const int4*)(dst + i));
        ushort4 r;
        r.x = (unsigned short)atomicAdd(&g_indeg[d.x], 1);
        r.y = (unsigned short)atomicAdd(&g_indeg[d.y], 1);
        r.z = (unsigned short)atomicAdd(&g_indeg[d.z], 1);
        r.w = (unsigned short)atomicAdd(&g_indeg[d.w], 1);
        *(ushort4*)(g_rank + i) = r;
    } else {
        for (; i < E; i++)
            g_rank[i] = (unsigned short)atomicAdd(&g_indeg[dst[i]], 1);
    }
}

// Block-wise inclusive scan of indeg (shfl); block totals -> g_bsums.
// Also emits dinv = rsqrt(indeg+1) so GEMM1 can fork right after this kernel.
__global__ __launch_bounds__(1024) void k_scan1(int n) {
    __shared__ int wsum[32];
    int t = threadIdx.x, lane = t & 31, w = t >> 5;
    int i = blockIdx.x * 1024 + t;
    int v = (i < n) ? g_indeg[i] : 0;
    int x = v;
    #pragma unroll
    for (int d = 1; d < 32; d <<= 1) {
        int y = __shfl_up_sync(0xffffffffu, x, d);
        if (lane >= d) x += y;
    }
    if (lane == 31) wsum[w] = x;
    __syncthreads();
    if (w == 0) {
        int y = wsum[lane];
        int z = y;
        #pragma unroll
        for (int d = 1; d < 32; d <<= 1) {
            int u = __shfl_up_sync(0xffffffffu, z, d);
            if (lane >= d) z += u;
        }
        wsum[lane] = z - y;  // exclusive warp offsets
    }
    __syncthreads();
    x += wsum[w];
    if (i < n) {
        g_incl[i] = x;
        g_dinv[i] = rsqrtf((float)(v + 1));
    }
    if (t == 1023) g_bsums[blockIdx.x] = x;
}

// Offsets: each 256-block lies in one 1024-chunk; warp 0 reduces bsums[0..chunk)
// (<=98 ints). Re-zeroes indeg for the next replay.
__global__ void k_scan3(int n) {
    __shared__ int s_pre;
    int chunk = (blockIdx.x * 256) >> 10;
    if (threadIdx.x < 32) {
        int acc = 0;
        for (int k = threadIdx.x; k < chunk; k += 32) acc += g_bsums[k];
        #pragma unroll
        for (int d = 16; d >= 1; d >>= 1) acc += __shfl_down_sync(0xffffffffu, acc, d);
        if (threadIdx.x == 0) s_pre = acc;
    }
    __syncthreads();
    int i = blockIdx.x * 256 + threadIdx.x;
    if (i < n) {
        int ind = g_indeg[i];
        int base = s_pre + g_incl[i];
        g_offs[i] = base - ind;
        if (i == n - 1) g_offs[n] = base;
        g_indeg[i] = 0;                      // ready for next replay
    }
}

// Atomic-free scatter: pos = offs[dst] + rank (rank precomputed in hist).
__global__ void k_fill(const int* __restrict__ src, const int* __restrict__ dst, int E) {
    int i = (blockIdx.x * blockDim.x + threadIdx.x) * 4;
    if (i + 4 <= E) {
        int4 s = __ldg((const int4*)(src + i));
        int4 d = __ldg((const int4*)(dst + i));
        ushort4 r = *(const ushort4*)(g_rank + i);
        g_csr[__ldg(&g_offs[d.x]) + r.x] = s.x;
        g_csr[__ldg(&g_offs[d.y]) + r.y] = s.y;
        g_csr[__ldg(&g_offs[d.z]) + r.z] = s.z;
        g_csr[__ldg(&g_offs[d.w]) + r.w] = s.w;
    } else {
        for (; i < E; i++) {
            g_csr[__ldg(&g_offs[dst[i]]) + g_rank[i]] = src[i];
        }
    }
}

// ---------------------------------------------------------------------------
// GEMM + fused dinv-scale + fp16 store: m[r] = fp16(dinv[r] * (X@W)[r]).
// T = float (layer 1 input) or __half (layer 2 input).
// 128 threads/block, 128 rows/block; 8x8 tile/thread via packed f32x2 FMA.
// ---------------------------------------------------------------------------
template <typename T>
__global__ __launch_bounds__(128) void k_gemm64h(const T* __restrict__ X,
                                                 const float* __restrict__ W,
                                                 __half* __restrict__ Yh, int n) {
    __shared__ float Ws[64 * 64];
    __shared__ float Xs[128 * 65];  // pad to 65 to avoid bank conflicts

    int t = threadIdx.x;
    #pragma unroll
    for (int i = t; i < 4096; i += 128) Ws[i] = W[i];

    int row0 = blockIdx.x * 128;
    for (int i = t; i < 8192; i += 128) {
        int r = i >> 6, c = i & 63;
        int gr = row0 + r;
        Xs[r * 65 + c] = (gr < n) ? (float)X[gr * 64 + c] : 0.f;
    }
    __syncthreads();

    int cg = t & 7;       // column group: cols [cg*8, cg*8+8)
    int rg = t >> 3;      // row group:    rows [rg*8, rg*8+8)

    unsigned long long acc[8][4];
    #pragma unroll
    for (int i = 0; i < 8; i++)
        #pragma unroll
        for (int j = 0; j < 4; j++) acc[i][j] = 0ull;

    #pragma unroll 4
    for (int k = 0; k < 64; k++) {
        ulonglong2 wA = *(const ulonglong2*)&Ws[k * 64 + cg * 8];
        ulonglong2 wB = *(const ulonglong2*)&Ws[k * 64 + cg * 8 + 4];
        #pragma unroll
        for (int i = 0; i < 8; i++) {
            unsigned long long xp = pack2(Xs[(rg * 8 + i) * 65 + k]);
            ffma2(acc[i][0], xp, wA.x);
            ffma2(acc[i][1], xp, wA.y);
            ffma2(acc[i][2], xp, wB.x);
            ffma2(acc[i][3], xp, wB.y);
        }
    }

    #pragma unroll
    for (int i = 0; i < 8; i++) {
        int gr = row0 + rg * 8 + i;
        if (gr < n) {
            float dv = __ldg(&g_dinv[gr]);
            float2 p0 = unpack2(acc[i][0]), p1 = unpack2(acc[i][1]);
            float2 p2 = unpack2(acc[i][2]), p3 = unpack2(acc[i][3]);
            uint4 pk;
            pk.x = h2_bits(__floats2half2_rn(p0.x * dv, p0.y * dv));
            pk.y = h2_bits(__floats2half2_rn(p1.x * dv, p1.y * dv));
            pk.z = h2_bits(__floats2half2_rn(p2.x * dv, p2.y * dv));
            pk.w = h2_bits(__floats2half2_rn(p3.x * dv, p3.y * dv));
            *(uint4*)&Yh[gr * 64 + cg * 8] = pk;
        }
    }
}

// ---------------------------------------------------------------------------
// Pull aggregation, paired-edge gathers + HADD2 in-batch accumulation.
// Warp = 1 node; 2 groups of 16 lanes; group g handles edges (e+2j+g);
// each lane gathers 8B (uint2 = 2 half2) of the 128B source row.
// Within a 16-edge batch: accumulate half2 pairs with 2 HADD2/pair (<=8 fp16
// adds), then flush to fp32 -- replaces 4cvt+4FADD/pair (issue-bound win).
// Tail: DYNAMIC pair loop (only the needed iterations issue).
// ---------------------------------------------------------------------------
template <bool HOUT>
__global__ __launch_bounds__(256) void k_agg(const uint2* __restrict__ xw,  // row = 16 uint2
                                             const float* __restrict__ bias,
                                             void* __restrict__ out, int n) {
    int v = (blockIdx.x * 256 + threadIdx.x) >> 5;
    int lane = threadIdx.x & 31;
    if (v >= n) return;
    int g = lane >> 4;       // edge-parity group (0: even edges, 1: odd edges)
    int c = lane & 15;       // 8-byte column slot within the 128B row

    float dv = g_dinv[v];
    float ax0 = 0.f, ay0 = 0.f, ax1 = 0.f, ay1 = 0.f;

    // self-loop message: group 0 only (fp32 path, exact)
    if (g == 0) {
        uint2 m = __ldg(&xw[v * 16 + c]);
        float2 a = h2f2(m.x), b = h2f2(m.y);
        ax0 = a.x; ay0 = a.y; ax1 = b.x; ay1 = b.y;
    }

    int e = __ldg(&g_offs[v]);
    int end = __ldg(&g_offs[v + 1]);

    // full batches: 16 edges (8 pairs); fp16 partial sums, fp32 flush per batch
    for (; e + 16 <= end; e += 16) {
        __half2 h01 = __float2half2_rn(0.f);
        __half2 h23 = __float2half2_rn(0.f);
        #pragma unroll
        for (int j = 0; j < 8; j++) {
            int idx = __ldg(&g_csr[e + 2 * j + g]);
            uint2 m = __ldg(&xw[idx * 16 + c]);
            h01 = __hadd2(h01, bits_h2(m.x));
            h23 = __hadd2(h23, bits_h2(m.y));
        }
        float2 f01 = __half22float2(h01), f23 = __half22float2(h23);
        ax0 += f01.x; ay0 += f01.y; ax1 += f23.x; ay1 += f23.y;
    }

    // dynamic tail: <16 edges; group g takes pairs e+2j+g while in range
    if (e < end) {
        __half2 h01 = __float2half2_rn(0.f);
        __half2 h23 = __float2half2_rn(0.f);
        int npairs = (end - e + 1 - g) >> 1;   // pairs this group participates in
        for (int j = 0; j < npairs; j++) {
            int idx = __ldg(&g_csr[e + 2 * j + g]);
            uint2 m = __ldg(&xw[idx * 16 + c]);
            h01 = __hadd2(h01, bits_h2(m.x));
            h23 = __hadd2(h23, bits_h2(m.y));
        }
        float2 f01 = __half22float2(h01), f23 = __half22float2(h23);
        ax0 += f01.x; ay0 += f01.y; ax1 += f23.x; ay1 += f23.y;
    }

    // combine the two edge groups
    ax0 += __shfl_down_sync(0xffffffffu, ax0, 16);
    ay0 += __shfl_down_sync(0xffffffffu, ay0, 16);
    ax1 += __shfl_down_sync(0xffffffffu, ax1, 16);
    ay1 += __shfl_down_sync(0xffffffffu, ay1, 16);

    if (g == 0) {
        float4 bv = __ldg((const float4*)(bias + c * 4));
        float r0 = fmaxf(fmaf(ax0, dv, bv.x), 0.f);
        float r1 = fmaxf(fmaf(ay0, dv, bv.y), 0.f);
        float r2 = fmaxf(fmaf(ax1, dv, bv.z), 0.f);
        float r3 = fmaxf(fmaf(ay1, dv, bv.w), 0.f);
        if (HOUT) {
            uint2 o;
            o.x = h2_bits(__floats2half2_rn(r0, r1));
            o.y = h2_bits(__floats2half2_rn(r2, r3));
            ((uint2*)out)[v * 16 + c] = o;
        } else {
            ((float4*)out)[v * 16 + c] = make_float4(r0, r1, r2, r3);
        }
    }
}

// ---------------------------------------------------------------------------
extern "C" void kernel_launch(void* const* d_in, const int* in_sizes, int n_in,
                              void* d_out, int out_size) {
    const float* x  = (const float*)d_in[0];
    const int*   ei = (const int*)d_in[1];
    const float* W1 = (const float*)d_in[2];
    const float* b1 = (const float*)d_in[3];
    const float* W2 = (const float*)d_in[4];
    const float* b2 = (const float*)d_in[5];
    float* out = (float*)d_out;

    int N = in_sizes[0] / 64;
    int E = in_sizes[1] / 2;
    const int* src = ei;
    const int* dst = ei + E;
    int E4 = E / 4;

    int nbN = (N + 255) / 256;
    int nbE4 = (E4 + 255) / 256;
    int nbScan = (N + 1023) / 1024;
    int nbAgg = (N + 7) / 8;       // 8 warps per 256-thread block
    int nbGemm = (N + 127) / 128;

    __half* hbuf;  cudaGetSymbolAddress((void**)&hbuf, g_hbuf);
    __half* hact;  cudaGetSymbolAddress((void**)&hact, g_hact);

    // One-time side stream + events (created on the pre-capture correctness
    // call; reused by every call -> identical, deterministic launch pattern).
    static cudaStream_t s1 = nullptr;
    static cudaEvent_t evFork = nullptr, evJoin = nullptr;
    static bool streamsOk = false;
    static bool tried = false;
    if (!tried) {
        tried = true;
        streamsOk = (cudaStreamCreateWithFlags(&s1, cudaStreamNonBlocking) == cudaSuccess) &&
                    (cudaEventCreateWithFlags(&evFork, cudaEventDisableTiming) == cudaSuccess) &&
                    (cudaEventCreateWithFlags(&evJoin, cudaEventDisableTiming) == cudaSuccess);
    }

    // CSR build prologue. indeg starts zero (globals on call 1, re-zeroed by
    // scan3 on every call).
    k_hist<<<nbE4, 256>>>(dst, E);
    k_scan1<<<nbScan, 1024>>>(N);   // also produces dinv

    if (streamsOk) {
        // Fork: GEMM1 (needs dinv only) overlaps scan3+fill on main stream.
        cudaEventRecord(evFork, 0);
        cudaStreamWaitEvent(s1, evFork, 0);
        k_gemm64h<float><<<nbGemm, 128, 0, s1>>>(x, W1, hbuf, N);
        cudaEventRecord(evJoin, s1);

        k_scan3<<<nbN, 256>>>(N);
        k_fill<<<nbE4, 256>>>(src, dst, E);

        cudaStreamWaitEvent(0, evJoin, 0);
    } else {
        k_gemm64h<float><<<nbGemm, 128>>>(x, W1, hbuf, N);
        k_scan3<<<nbN, 256>>>(N);
        k_fill<<<nbE4, 256>>>(src, dst, E);
    }

    // Layer 1 aggregate (fp16 h), then layer 2 (hbuf reused for m2 -- strictly
    // sequential on the main stream, so no overlap with agg1's reads)
    k_agg<true><<<nbAgg, 256>>>((const uint2*)hbuf, b1, hact, N);
    k_gemm64h<__half><<<nbGemm, 128>>>(hact, W2, hbuf, N);
    k_agg<false><<<nbAgg, 256>>>((const uint2*)hbuf, b2, out, N);
}